// round 8
// baseline (speedup 1.0000x reference)
#include <cuda_runtime.h>
#include <cuda_fp16.h>
#include <math.h>
#include <stdint.h>

// Problem constants
#define BB 4
#define NN 2048
#define CC 1024
#define HH 16
#define HD 64
#define M_TOT (BB*NN)    // 8192
#define N3C   (3*CC)     // 3072
#define K_TOT CC         // 1024

#define LOG2E 1.4426950408889634f
#define QSCALE (0.125f * LOG2E)   // 64^-0.5 * log2(e), folded into Q

// Scratch (static device globals — allocation-free per harness rules)
__device__ __half g_x [M_TOT * CC];        // x = inputs + PE (fp16)  [8192,1024]
__device__ __half g_wt[N3C * CC];          // W^T (fp16)              [3072,1024]
__device__ __half g_q [BB*HH*NN*HD];       // [B,H,N,hd], pre-scaled by QSCALE
__device__ __half g_k [BB*HH*NN*HD];       // [B,H,N,hd]
__device__ __half g_vt[BB*HH*HD*NN];       // V transposed: [B,H,hd,N]

// ---------------------------------------------------------------------------
// Helpers
// ---------------------------------------------------------------------------
__device__ __forceinline__ void mma_f16(float* c, const uint32_t* a,
                                        uint32_t b0, uint32_t b1) {
    asm volatile(
        "mma.sync.aligned.m16n8k16.row.col.f32.f16.f16.f32 "
        "{%0,%1,%2,%3}, {%4,%5,%6,%7}, {%8,%9}, {%0,%1,%2,%3};"
        : "+f"(c[0]), "+f"(c[1]), "+f"(c[2]), "+f"(c[3])
        : "r"(a[0]), "r"(a[1]), "r"(a[2]), "r"(a[3]), "r"(b0), "r"(b1));
}

__device__ __forceinline__ void ldsm_x4(uint32_t* r, uint32_t a) {
    asm volatile("ldmatrix.sync.aligned.m8n8.x4.shared.b16 {%0,%1,%2,%3}, [%4];"
        : "=r"(r[0]), "=r"(r[1]), "=r"(r[2]), "=r"(r[3]) : "r"(a));
}

__device__ __forceinline__ uint32_t f2h2(float lo, float hi) {
    __half2 h = __floats2half2_rn(lo, hi);
    return *(uint32_t*)&h;
}

__device__ __forceinline__ float exp2f_fast(float x) {
    float y;
    asm("ex2.approx.ftz.f32 %0, %1;" : "=f"(y) : "f"(x));
    return y;
}

__device__ __forceinline__ uint32_t smem_u32(const void* p) {
    uint32_t a;
    asm("{ .reg .u64 t; cvta.to.shared.u64 t, %1; cvt.u32.u64 %0, t; }"
        : "=r"(a) : "l"(p));
    return a;
}

#define CP_ASYNC16(dst, src) \
    asm volatile("cp.async.cg.shared.global [%0], [%1], 16;" \
        :: "r"(dst), "l"(src) : "memory")
#define CP_COMMIT() asm volatile("cp.async.commit_group;" ::: "memory")
#define CP_WAIT1()  asm volatile("cp.async.wait_group 1;" ::: "memory")
#define CP_WAIT2()  asm volatile("cp.async.wait_group 2;" ::: "memory")

// ---------------------------------------------------------------------------
// Kernel 1: x = inputs + sinusoidal PE -> fp16
// ---------------------------------------------------------------------------
__global__ void pe_add_kernel(const float* __restrict__ in) {
    int idx = blockIdx.x * blockDim.x + threadIdx.x;
    if (idx >= NN * CC) return;
    int c = idx & (CC - 1);
    int n = idx >> 10;
    float e = (float)(2 * (c >> 1)) / (float)CC;
    float rate = powf(10000.0f, -e);
    float ang = (float)n * rate;
    float s, co;
    sincosf(ang, &s, &co);
    float pe = (c & 1) ? co : s;
#pragma unroll
    for (int b = 0; b < BB; b++) {
        g_x[b * (NN * CC) + idx] = __float2half_rn(in[b * (NN * CC) + idx] + pe);
    }
}

// ---------------------------------------------------------------------------
// Kernel 1b: W^T -> fp16. W [1024,3072] -> g_wt [3072,1024]
// ---------------------------------------------------------------------------
__global__ __launch_bounds__(256) void wt_kernel(const float* __restrict__ W) {
    __shared__ float t[32][33];
    int tx = threadIdx.x, ty = threadIdx.y;
    int n0 = blockIdx.x * 32;
    int k0 = blockIdx.y * 32;
#pragma unroll
    for (int i = 0; i < 32; i += 8)
        t[ty + i][tx] = W[(size_t)(k0 + ty + i) * N3C + n0 + tx];
    __syncthreads();
#pragma unroll
    for (int i = 0; i < 32; i += 8)
        g_wt[(size_t)(n0 + ty + i) * K_TOT + k0 + tx] = __float2half_rn(t[tx][ty + i]);
}

// ---------------------------------------------------------------------------
// Kernel 2: QKV GEMM, mma.sync fp16 (m16n8k16), 3-stage cp.async pipeline,
// ldmatrix fragment loads. Epilogue: Q pre-scaled; V transposed.
// ---------------------------------------------------------------------------
#define GBM 128
#define GBN 128
#define GBK 32
#define GSTRH 40                 // halves per row (80B, LDSM conflict-free)
#define GNKT (K_TOT / GBK)       // 32
#define QSTH (GBM * GSTRH)       // halves per tile per stage (5120)
#define QSM_BYTES (3 * 2 * QSTH * 2)   // 61440

__global__ __launch_bounds__(256, 2) void qkv_mma_kernel() {
    extern __shared__ char qsm[];
    const uint32_t smb = smem_u32(qsm);

    const int tid  = threadIdx.x;
    const int wid  = tid >> 5;
    const int lane = tid & 31;
    const int g    = lane >> 2;    // 0..7
    const int t    = lane & 3;     // 0..3
    const int lrow = lane & 15;    // ldmatrix row within 16
    const int lcol = (lane >> 4) << 3;   // 0 or 8 (k offset)
    const int wm   = (wid & 1) * 64;
    const int wn   = (wid >> 1) * 32;
    const int row0 = blockIdx.y * GBM;
    const int col0 = blockIdx.x * GBN;

    float acc[4][4][4];
#pragma unroll
    for (int mi = 0; mi < 4; mi++)
#pragma unroll
        for (int ni = 0; ni < 4; ni++)
#pragma unroll
            for (int j = 0; j < 4; j++) acc[mi][ni][j] = 0.0f;

    auto issue = [&](int s, int kt) {
        const int k0 = kt * GBK;
        const uint32_t dA = smb + (uint32_t)(s * 2 * QSTH) * 2;
        const uint32_t dB = dA + (uint32_t)QSTH * 2;
#pragma unroll
        for (int p = 0; p < 2; p++) {
            int idx = p * 256 + tid;            // 512 chunks per tile
            int row = idx >> 2, ch = (idx & 3) * 8;
            CP_ASYNC16(dA + (uint32_t)(row * GSTRH + ch) * 2,
                       &g_x[(size_t)(row0 + row) * K_TOT + k0 + ch]);
            CP_ASYNC16(dB + (uint32_t)(row * GSTRH + ch) * 2,
                       &g_wt[(size_t)(col0 + row) * K_TOT + k0 + ch]);
        }
    };

    issue(0, 0); CP_COMMIT();
    issue(1, 1); CP_COMMIT();

    for (int kt = 0; kt < GNKT; kt++) {
        CP_WAIT1();
        __syncthreads();
        const uint32_t sbase = smb + (uint32_t)((kt % 3) * 2 * QSTH) * 2;
        const uint32_t aaddr = sbase + (uint32_t)((wm + lrow) * GSTRH + lcol) * 2;
        const uint32_t baddr = sbase + (uint32_t)QSTH * 2
                             + (uint32_t)((wn + lrow) * GSTRH + lcol) * 2;

#pragma unroll
        for (int ks = 0; ks < 2; ks++) {
            uint32_t af[4][4], bf4[2][4];
#pragma unroll
            for (int mi = 0; mi < 4; mi++)
                ldsm_x4(af[mi], aaddr + mi * (16 * GSTRH * 2) + ks * 32);
#pragma unroll
            for (int p = 0; p < 2; p++)
                ldsm_x4(bf4[p], baddr + p * (16 * GSTRH * 2) + ks * 32);
#pragma unroll
            for (int mi = 0; mi < 4; mi++) {
                mma_f16(acc[mi][0], af[mi], bf4[0][0], bf4[0][2]);
                mma_f16(acc[mi][1], af[mi], bf4[0][1], bf4[0][3]);
                mma_f16(acc[mi][2], af[mi], bf4[1][0], bf4[1][2]);
                mma_f16(acc[mi][3], af[mi], bf4[1][1], bf4[1][3]);
            }
        }
        __syncthreads();
        if (kt + 2 < GNKT) issue((kt + 2) % 3, kt + 2);
        CP_COMMIT();
    }

    // Epilogue: Q pre-scaled by QSCALE; Q/K -> [B,H,N,hd], V -> [B,H,hd,N]
#pragma unroll
    for (int mi = 0; mi < 4; mi++) {
        const int row = row0 + wm + mi * 16 + g;
        const int b = row >> 11;
        const int n = row & (NN - 1);
#pragma unroll
        for (int ni = 0; ni < 4; ni++) {
            const int col = col0 + wn + ni * 8 + 2 * t;
            const int tt = col >> 10;
            const int h = (col >> 6) & 15;
            const int d = col & 63;
            const size_t bh = (size_t)(b * HH + h);
            if (tt == 0) {
                __half2* p0 = (__half2*)(g_q + (bh * NN + n) * HD + d);
                *p0 = __floats2half2_rn(acc[mi][ni][0] * QSCALE, acc[mi][ni][1] * QSCALE);
                __half2* p1 = (__half2*)(g_q + (bh * NN + n + 8) * HD + d);
                *p1 = __floats2half2_rn(acc[mi][ni][2] * QSCALE, acc[mi][ni][3] * QSCALE);
            } else if (tt == 1) {
                __half2* p0 = (__half2*)(g_k + (bh * NN + n) * HD + d);
                *p0 = __floats2half2_rn(acc[mi][ni][0], acc[mi][ni][1]);
                __half2* p1 = (__half2*)(g_k + (bh * NN + n + 8) * HD + d);
                *p1 = __floats2half2_rn(acc[mi][ni][2], acc[mi][ni][3]);
            } else {
                __half* vt = g_vt + bh * HD * NN;
                vt[(size_t)d * NN + n]           = __float2half_rn(acc[mi][ni][0]);
                vt[(size_t)(d + 1) * NN + n]     = __float2half_rn(acc[mi][ni][1]);
                vt[(size_t)d * NN + n + 8]       = __float2half_rn(acc[mi][ni][2]);
                vt[(size_t)(d + 1) * NN + n + 8] = __float2half_rn(acc[mi][ni][3]);
            }
        }
    }
}

// ---------------------------------------------------------------------------
// Kernel 3: Flash attention, mma.sync fp16 (m16n8k16), log2-domain softmax,
// ldmatrix fragment loads, Q fragments hoisted out of the key loop.
// ---------------------------------------------------------------------------
#define FBM 128
#define FBN 64
#define FNT (NN / FBN)     // 32
#define STRH 72            // halves per row (144B, LDSM conflict-free)
// byte offsets into dynamic smem
#define OFF_Q   0
#define OFF_K   (OFF_Q + FBM*STRH*2)          // 18432
#define OFF_VT  (OFF_K + 2*FBN*STRH*2)        // 36864
#define OFF_MQ  (OFF_VT + 2*FBN*STRH*2)       // 55296 (floats)
#define OFF_MK  (OFF_MQ + FBM*4)              // 55808
#define FSM_BYTES (OFF_MK + 2*FBN*4)          // 56320

__global__ __launch_bounds__(128, 2) void attn_mma_kernel(const float* __restrict__ mask,
                                                          float* __restrict__ out) {
    extern __shared__ char smc[];
    const uint32_t smb = smem_u32(smc);
    const uint32_t sQ  = smb + OFF_Q;
    const uint32_t sK  = smb + OFF_K;
    const uint32_t sVT = smb + OFF_VT;
    const uint32_t sMQ = smb + OFF_MQ;
    const uint32_t sMK = smb + OFF_MK;

    float* mq = (float*)(smc + OFF_MQ);
    float* mk = (float*)(smc + OFF_MK);

    const int bh = blockIdx.y;
    const int b  = bh >> 4;
    const int h  = bh & 15;
    const int r0 = blockIdx.x * FBM;

    const int tid  = threadIdx.x;
    const int wid  = tid >> 5;
    const int lane = tid & 31;
    const int g    = lane >> 2;
    const int t    = lane & 3;
    const int lrow = lane & 15;
    const int lcol = (lane >> 4) << 3;
    const int wm   = wid * 32;

    const __half* Qg  = g_q  + (size_t)bh * NN * HD;
    const __half* Kg  = g_k  + (size_t)bh * NN * HD;
    const __half* Vtg = g_vt + (size_t)bh * HD * NN;

    auto issue_kv = [&](int kt) {
        const int buf = kt & 1;
        const int c0 = kt * FBN;
#pragma unroll
        for (int p = 0; p < 4; p++) {
            int idx = p * 128 + tid;          // 512 chunks each
            int r = idx >> 3, ch = (idx & 7) * 8;
            CP_ASYNC16(sK + (uint32_t)((buf * FBN + r) * STRH + ch) * 2,
                       Kg + (size_t)(c0 + r) * HD + ch);
            CP_ASYNC16(sVT + (uint32_t)((buf * FBN + r) * STRH + ch) * 2,
                       Vtg + (size_t)r * NN + c0 + ch);
        }
        if (tid < 16)
            CP_ASYNC16(sMK + (uint32_t)(buf * FBN + tid * 4) * 4,
                       mask + (size_t)b * NN + c0 + tid * 4);
    };

    // Prologue: Q tile + row mask, then KV tiles 0 and 1
    {
#pragma unroll
        for (int p = 0; p < 8; p++) {
            int idx = p * 128 + tid;          // 1024 chunks
            int r = idx >> 3, ch = (idx & 7) * 8;
            CP_ASYNC16(sQ + (uint32_t)(r * STRH + ch) * 2,
                       Qg + (size_t)(r0 + r) * HD + ch);
        }
        if (tid < 32)
            CP_ASYNC16(sMQ + (uint32_t)(tid * 4) * 4,
                       mask + (size_t)b * NN + r0 + tid * 4);
        CP_COMMIT();
        issue_kv(0); CP_COMMIT();
        issue_kv(1); CP_COMMIT();
    }

    // Hoist Q fragments (tile-invariant): wait for Q group only, load once.
    CP_WAIT2();
    __syncthreads();
    uint32_t qf[2][4][4];   // [mi][ks][frag]
    {
        const uint32_t qaddr = sQ + (uint32_t)((wm + lrow) * STRH + lcol) * 2;
#pragma unroll
        for (int mi = 0; mi < 2; mi++)
#pragma unroll
            for (int ks = 0; ks < 4; ks++)
                ldsm_x4(qf[mi][ks], qaddr + mi * (16 * STRH * 2) + ks * 32);
    }

    float o[2][8][4];
    float m_lo[2], m_hi[2], l_lo[2], l_hi[2];
#pragma unroll
    for (int mi = 0; mi < 2; mi++) {
        m_lo[mi] = -1e30f; m_hi[mi] = -1e30f;
        l_lo[mi] = 0.0f;   l_hi[mi] = 0.0f;
#pragma unroll
        for (int ni = 0; ni < 8; ni++)
#pragma unroll
            for (int j = 0; j < 4; j++) o[mi][ni][j] = 0.0f;
    }

    const uint32_t FULL = 0xffffffffu;

    for (int kt = 0; kt < FNT; kt++) {
        CP_WAIT1();
        __syncthreads();
        const int kb = (kt & 1) * FBN;
        const uint32_t kaddr = sK  + (uint32_t)((kb + lrow) * STRH + lcol) * 2;
        const uint32_t vaddr = sVT + (uint32_t)((kb + lrow) * STRH + lcol) * 2;

        // row-mask values (log2e-scaled)
        const float mq_l2[2] = { mq[wm + g] * LOG2E,      mq[wm + 16 + g] * LOG2E };
        const float mq_h2[2] = { mq[wm + g + 8] * LOG2E,  mq[wm + 16 + g + 8] * LOG2E };
        float k0v[8], k1v[8];
#pragma unroll
        for (int ni = 0; ni < 8; ni++) {
            k0v[ni] = mk[kb + ni * 8 + 2 * t];
            k1v[ni] = mk[kb + ni * 8 + 2 * t + 1];
        }

        // ---- S = Q K^T : 4 k16 steps, ldmatrix K fragments ----
        float sA[2][8][4];
#pragma unroll
        for (int mi = 0; mi < 2; mi++)
#pragma unroll
            for (int ni = 0; ni < 8; ni++)
#pragma unroll
                for (int j = 0; j < 4; j++) sA[mi][ni][j] = 0.0f;

#pragma unroll
        for (int ks = 0; ks < 4; ks++) {
#pragma unroll
            for (int p = 0; p < 4; p++) {
                uint32_t kf[4];
                ldsm_x4(kf, kaddr + p * (16 * STRH * 2) + ks * 32);
                mma_f16(sA[0][2 * p],     qf[0][ks], kf[0], kf[2]);
                mma_f16(sA[0][2 * p + 1], qf[0][ks], kf[1], kf[3]);
                mma_f16(sA[1][2 * p],     qf[1][ks], kf[0], kf[2]);
                mma_f16(sA[1][2 * p + 1], qf[1][ks], kf[1], kf[3]);
            }
        }

        // ---- mask (1 fma) + online softmax in log2 domain ----
#pragma unroll
        for (int mi = 0; mi < 2; mi++) {
            float mx_lo = -1e30f, mx_hi = -1e30f;
#pragma unroll
            for (int ni = 0; ni < 8; ni++) {
                sA[mi][ni][0] = fmaf(-mq_l2[mi], k0v[ni], sA[mi][ni][0]);
                sA[mi][ni][1] = fmaf(-mq_l2[mi], k1v[ni], sA[mi][ni][1]);
                sA[mi][ni][2] = fmaf(-mq_h2[mi], k0v[ni], sA[mi][ni][2]);
                sA[mi][ni][3] = fmaf(-mq_h2[mi], k1v[ni], sA[mi][ni][3]);
                mx_lo = fmaxf(mx_lo, fmaxf(sA[mi][ni][0], sA[mi][ni][1]));
                mx_hi = fmaxf(mx_hi, fmaxf(sA[mi][ni][2], sA[mi][ni][3]));
            }
            mx_lo = fmaxf(mx_lo, __shfl_xor_sync(FULL, mx_lo, 1));
            mx_lo = fmaxf(mx_lo, __shfl_xor_sync(FULL, mx_lo, 2));
            mx_hi = fmaxf(mx_hi, __shfl_xor_sync(FULL, mx_hi, 1));
            mx_hi = fmaxf(mx_hi, __shfl_xor_sync(FULL, mx_hi, 2));

            const float mnew_lo = fmaxf(m_lo[mi], mx_lo);
            const float mnew_hi = fmaxf(m_hi[mi], mx_hi);
            const float fac_lo = exp2f_fast(m_lo[mi] - mnew_lo);
            const float fac_hi = exp2f_fast(m_hi[mi] - mnew_hi);

            float rs_lo = 0.0f, rs_hi = 0.0f;
#pragma unroll
            for (int ni = 0; ni < 8; ni++) {
                sA[mi][ni][0] = exp2f_fast(sA[mi][ni][0] - mnew_lo);
                sA[mi][ni][1] = exp2f_fast(sA[mi][ni][1] - mnew_lo);
                sA[mi][ni][2] = exp2f_fast(sA[mi][ni][2] - mnew_hi);
                sA[mi][ni][3] = exp2f_fast(sA[mi][ni][3] - mnew_hi);
                rs_lo += sA[mi][ni][0] + sA[mi][ni][1];
                rs_hi += sA[mi][ni][2] + sA[mi][ni][3];
            }
            rs_lo += __shfl_xor_sync(FULL, rs_lo, 1);
            rs_lo += __shfl_xor_sync(FULL, rs_lo, 2);
            rs_hi += __shfl_xor_sync(FULL, rs_hi, 1);
            rs_hi += __shfl_xor_sync(FULL, rs_hi, 2);

            l_lo[mi] = fmaf(l_lo[mi], fac_lo, rs_lo);  m_lo[mi] = mnew_lo;
            l_hi[mi] = fmaf(l_hi[mi], fac_hi, rs_hi);  m_hi[mi] = mnew_hi;
#pragma unroll
            for (int ni = 0; ni < 8; ni++) {
                o[mi][ni][0] *= fac_lo; o[mi][ni][1] *= fac_lo;
                o[mi][ni][2] *= fac_hi; o[mi][ni][3] *= fac_hi;
            }
        }

        // ---- O += P V : P A-fragments = packed S C-fragments; LDSM V ----
#pragma unroll
        for (int ks = 0; ks < 4; ks++) {
            uint32_t af[2][4];
#pragma unroll
            for (int mi = 0; mi < 2; mi++) {
                af[mi][0] = f2h2(sA[mi][2 * ks][0],     sA[mi][2 * ks][1]);
                af[mi][1] = f2h2(sA[mi][2 * ks][2],     sA[mi][2 * ks][3]);
                af[mi][2] = f2h2(sA[mi][2 * ks + 1][0], sA[mi][2 * ks + 1][1]);
                af[mi][3] = f2h2(sA[mi][2 * ks + 1][2], sA[mi][2 * ks + 1][3]);
            }
#pragma unroll
            for (int p = 0; p < 4; p++) {
                uint32_t vf[4];
                ldsm_x4(vf, vaddr + p * (16 * STRH * 2) + ks * 32);
                mma_f16(o[0][2 * p],     af[0], vf[0], vf[2]);
                mma_f16(o[0][2 * p + 1], af[0], vf[1], vf[3]);
                mma_f16(o[1][2 * p],     af[1], vf[0], vf[2]);
                mma_f16(o[1][2 * p + 1], af[1], vf[1], vf[3]);
            }
        }

        __syncthreads();
        if (kt + 2 < FNT) issue_kv(kt + 2);
        CP_COMMIT();
    }

    // Output: out[b][n][h*64+d]
#pragma unroll
    for (int mi = 0; mi < 2; mi++) {
        const float inv_lo = 1.0f / l_lo[mi];
        const float inv_hi = 1.0f / l_hi[mi];
        const int row = r0 + wm + mi * 16 + g;
#pragma unroll
        for (int ni = 0; ni < 8; ni++) {
            const int col = h * HD + ni * 8 + 2 * t;
            *(float2*)&out[((size_t)(b * NN + row)) * CC + col] =
                make_float2(o[mi][ni][0] * inv_lo, o[mi][ni][1] * inv_lo);
            *(float2*)&out[((size_t)(b * NN + row + 8)) * CC + col] =
                make_float2(o[mi][ni][2] * inv_hi, o[mi][ni][3] * inv_hi);
        }
    }
}

// ---------------------------------------------------------------------------
extern "C" void kernel_launch(void* const* d_in, const int* in_sizes, int n_in,
                              void* d_out, int out_size) {
    const float* inputs = (const float*)d_in[0];   // [B,N,C]
    const float* mask   = (const float*)d_in[1];   // [B,N]
    const float* W      = (const float*)d_in[2];   // [C,3C]
    float* out = (float*)d_out;                    // [B,N,C]

    cudaFuncSetAttribute((const void*)qkv_mma_kernel,
                         cudaFuncAttributeMaxDynamicSharedMemorySize, QSM_BYTES);
    cudaFuncSetAttribute((const void*)attn_mma_kernel,
                         cudaFuncAttributeMaxDynamicSharedMemorySize, FSM_BYTES);

    pe_add_kernel<<<(NN * CC + 255) / 256, 256>>>(inputs);
    wt_kernel<<<dim3(N3C / 32, K_TOT / 32), dim3(32, 8)>>>(W);
    qkv_mma_kernel<<<dim3(N3C / GBN, M_TOT / GBM), 256, QSM_BYTES>>>();
    attn_mma_kernel<<<dim3(NN / FBM, BB * HH), 128, FSM_BYTES>>>(mask, out);
}

// round 9
// speedup vs baseline: 1.0280x; 1.0280x over previous
#include <cuda_runtime.h>
#include <cuda_fp16.h>
#include <math.h>
#include <stdint.h>

// Problem constants
#define BB 4
#define NN 2048
#define CC 1024
#define HH 16
#define HD 64
#define M_TOT (BB*NN)    // 8192
#define N3C   (3*CC)     // 3072
#define K_TOT CC         // 1024

#define LOG2E 1.4426950408889634f
#define QSCALE (0.125f * LOG2E)   // 64^-0.5 * log2(e), folded into Q

// Scratch (static device globals — allocation-free per harness rules)
__device__ __half g_x [M_TOT * CC];        // x = inputs + PE (fp16)  [8192,1024]
__device__ __half g_wt[N3C * CC];          // W^T (fp16)              [3072,1024]
__device__ __half g_q [BB*HH*NN*HD];       // [B,H,N,hd], pre-scaled by QSCALE
__device__ __half g_k [BB*HH*NN*HD];       // [B,H,N,hd]
__device__ __half g_vt[BB*HH*HD*NN];       // V transposed: [B,H,hd,N]

// ---------------------------------------------------------------------------
// Helpers
// ---------------------------------------------------------------------------
__device__ __forceinline__ void mma_f16(float* c, const uint32_t* a,
                                        uint32_t b0, uint32_t b1) {
    asm volatile(
        "mma.sync.aligned.m16n8k16.row.col.f32.f16.f16.f32 "
        "{%0,%1,%2,%3}, {%4,%5,%6,%7}, {%8,%9}, {%0,%1,%2,%3};"
        : "+f"(c[0]), "+f"(c[1]), "+f"(c[2]), "+f"(c[3])
        : "r"(a[0]), "r"(a[1]), "r"(a[2]), "r"(a[3]), "r"(b0), "r"(b1));
}

__device__ __forceinline__ void ldsm_x4(uint32_t* r, uint32_t a) {
    asm volatile("ldmatrix.sync.aligned.m8n8.x4.shared.b16 {%0,%1,%2,%3}, [%4];"
        : "=r"(r[0]), "=r"(r[1]), "=r"(r[2]), "=r"(r[3]) : "r"(a));
}

__device__ __forceinline__ uint32_t f2h2(float lo, float hi) {
    __half2 h = __floats2half2_rn(lo, hi);
    return *(uint32_t*)&h;
}

__device__ __forceinline__ float exp2f_fast(float x) {
    float y;
    asm("ex2.approx.ftz.f32 %0, %1;" : "=f"(y) : "f"(x));
    return y;
}

__device__ __forceinline__ uint32_t smem_u32(const void* p) {
    uint32_t a;
    asm("{ .reg .u64 t; cvta.to.shared.u64 t, %1; cvt.u32.u64 %0, t; }"
        : "=r"(a) : "l"(p));
    return a;
}

#define CP_ASYNC16(dst, src) \
    asm volatile("cp.async.cg.shared.global [%0], [%1], 16;" \
        :: "r"(dst), "l"(src) : "memory")
#define CP_COMMIT() asm volatile("cp.async.commit_group;" ::: "memory")
#define CP_WAIT1()  asm volatile("cp.async.wait_group 1;" ::: "memory")

// ---------------------------------------------------------------------------
// Kernel 1: x = inputs + sinusoidal PE -> fp16
// ---------------------------------------------------------------------------
__global__ void pe_add_kernel(const float* __restrict__ in) {
    int idx = blockIdx.x * blockDim.x + threadIdx.x;
    if (idx >= NN * CC) return;
    int c = idx & (CC - 1);
    int n = idx >> 10;
    float e = (float)(2 * (c >> 1)) / (float)CC;
    float rate = powf(10000.0f, -e);
    float ang = (float)n * rate;
    float s, co;
    sincosf(ang, &s, &co);
    float pe = (c & 1) ? co : s;
#pragma unroll
    for (int b = 0; b < BB; b++) {
        g_x[b * (NN * CC) + idx] = __float2half_rn(in[b * (NN * CC) + idx] + pe);
    }
}

// ---------------------------------------------------------------------------
// Kernel 1b: W^T -> fp16. W [1024,3072] -> g_wt [3072,1024]
// ---------------------------------------------------------------------------
__global__ __launch_bounds__(256) void wt_kernel(const float* __restrict__ W) {
    __shared__ float t[32][33];
    int tx = threadIdx.x, ty = threadIdx.y;
    int n0 = blockIdx.x * 32;
    int k0 = blockIdx.y * 32;
#pragma unroll
    for (int i = 0; i < 32; i += 8)
        t[ty + i][tx] = W[(size_t)(k0 + ty + i) * N3C + n0 + tx];
    __syncthreads();
#pragma unroll
    for (int i = 0; i < 32; i += 8)
        g_wt[(size_t)(n0 + ty + i) * K_TOT + k0 + tx] = __float2half_rn(t[tx][ty + i]);
}

// ---------------------------------------------------------------------------
// Kernel 2: QKV GEMM, mma.sync fp16 (m16n8k16), 3-stage cp.async pipeline,
// ldmatrix fragment loads. Epilogue: Q pre-scaled; V transposed.
// ---------------------------------------------------------------------------
#define GBM 128
#define GBN 128
#define GBK 32
#define GSTRH 40                 // halves per row (80B, LDSM conflict-free)
#define GNKT (K_TOT / GBK)       // 32
#define QSTH (GBM * GSTRH)       // halves per tile per stage (5120)
#define QSM_BYTES (3 * 2 * QSTH * 2)   // 61440

__global__ __launch_bounds__(256, 2) void qkv_mma_kernel() {
    extern __shared__ char qsm[];
    const uint32_t smb = smem_u32(qsm);

    const int tid  = threadIdx.x;
    const int wid  = tid >> 5;
    const int lane = tid & 31;
    const int g    = lane >> 2;    // 0..7
    const int t    = lane & 3;     // 0..3
    const int lrow = lane & 15;    // ldmatrix row within 16
    const int lcol = (lane >> 4) << 3;   // 0 or 8 (k offset)
    const int wm   = (wid & 1) * 64;
    const int wn   = (wid >> 1) * 32;
    const int row0 = blockIdx.y * GBM;
    const int col0 = blockIdx.x * GBN;

    float acc[4][4][4];
#pragma unroll
    for (int mi = 0; mi < 4; mi++)
#pragma unroll
        for (int ni = 0; ni < 4; ni++)
#pragma unroll
            for (int j = 0; j < 4; j++) acc[mi][ni][j] = 0.0f;

    auto issue = [&](int s, int kt) {
        const int k0 = kt * GBK;
        const uint32_t dA = smb + (uint32_t)(s * 2 * QSTH) * 2;
        const uint32_t dB = dA + (uint32_t)QSTH * 2;
#pragma unroll
        for (int p = 0; p < 2; p++) {
            int idx = p * 256 + tid;            // 512 chunks per tile
            int row = idx >> 2, ch = (idx & 3) * 8;
            CP_ASYNC16(dA + (uint32_t)(row * GSTRH + ch) * 2,
                       &g_x[(size_t)(row0 + row) * K_TOT + k0 + ch]);
            CP_ASYNC16(dB + (uint32_t)(row * GSTRH + ch) * 2,
                       &g_wt[(size_t)(col0 + row) * K_TOT + k0 + ch]);
        }
    };

    issue(0, 0); CP_COMMIT();
    issue(1, 1); CP_COMMIT();

    for (int kt = 0; kt < GNKT; kt++) {
        CP_WAIT1();
        __syncthreads();
        const uint32_t sbase = smb + (uint32_t)((kt % 3) * 2 * QSTH) * 2;
        const uint32_t aaddr = sbase + (uint32_t)((wm + lrow) * GSTRH + lcol) * 2;
        const uint32_t baddr = sbase + (uint32_t)QSTH * 2
                             + (uint32_t)((wn + lrow) * GSTRH + lcol) * 2;

#pragma unroll
        for (int ks = 0; ks < 2; ks++) {
            uint32_t af[4][4], bf4[2][4];
#pragma unroll
            for (int mi = 0; mi < 4; mi++)
                ldsm_x4(af[mi], aaddr + mi * (16 * GSTRH * 2) + ks * 32);
#pragma unroll
            for (int p = 0; p < 2; p++)
                ldsm_x4(bf4[p], baddr + p * (16 * GSTRH * 2) + ks * 32);
#pragma unroll
            for (int mi = 0; mi < 4; mi++) {
                mma_f16(acc[mi][0], af[mi], bf4[0][0], bf4[0][2]);
                mma_f16(acc[mi][1], af[mi], bf4[0][1], bf4[0][3]);
                mma_f16(acc[mi][2], af[mi], bf4[1][0], bf4[1][2]);
                mma_f16(acc[mi][3], af[mi], bf4[1][1], bf4[1][3]);
            }
        }
        __syncthreads();
        if (kt + 2 < GNKT) issue((kt + 2) % 3, kt + 2);
        CP_COMMIT();
    }

    // Epilogue: Q pre-scaled by QSCALE; Q/K -> [B,H,N,hd], V -> [B,H,hd,N]
#pragma unroll
    for (int mi = 0; mi < 4; mi++) {
        const int row = row0 + wm + mi * 16 + g;
        const int b = row >> 11;
        const int n = row & (NN - 1);
#pragma unroll
        for (int ni = 0; ni < 4; ni++) {
            const int col = col0 + wn + ni * 8 + 2 * t;
            const int tt = col >> 10;
            const int h = (col >> 6) & 15;
            const int d = col & 63;
            const size_t bh = (size_t)(b * HH + h);
            if (tt == 0) {
                __half2* p0 = (__half2*)(g_q + (bh * NN + n) * HD + d);
                *p0 = __floats2half2_rn(acc[mi][ni][0] * QSCALE, acc[mi][ni][1] * QSCALE);
                __half2* p1 = (__half2*)(g_q + (bh * NN + n + 8) * HD + d);
                *p1 = __floats2half2_rn(acc[mi][ni][2] * QSCALE, acc[mi][ni][3] * QSCALE);
            } else if (tt == 1) {
                __half2* p0 = (__half2*)(g_k + (bh * NN + n) * HD + d);
                *p0 = __floats2half2_rn(acc[mi][ni][0], acc[mi][ni][1]);
                __half2* p1 = (__half2*)(g_k + (bh * NN + n + 8) * HD + d);
                *p1 = __floats2half2_rn(acc[mi][ni][2], acc[mi][ni][3]);
            } else {
                __half* vt = g_vt + bh * HD * NN;
                vt[(size_t)d * NN + n]           = __float2half_rn(acc[mi][ni][0]);
                vt[(size_t)(d + 1) * NN + n]     = __float2half_rn(acc[mi][ni][1]);
                vt[(size_t)d * NN + n + 8]       = __float2half_rn(acc[mi][ni][2]);
                vt[(size_t)(d + 1) * NN + n + 8] = __float2half_rn(acc[mi][ni][3]);
            }
        }
    }
}

// ---------------------------------------------------------------------------
// Kernel 3: Flash attention, mma.sync fp16 (m16n8k16), log2-domain softmax,
// ldmatrix fragment loads WITHOUT the Q-fragment hoist (regs were the R8
// regression: hoist -> 255-reg cap -> spills). Q fragments are ldmatrix'd
// per k-step; P packed to half2 right after softmax so sA dies before PV.
// ---------------------------------------------------------------------------
#define FBM 128
#define FBN 64
#define FNT (NN / FBN)     // 32
#define STRH 72            // halves per row (144B, LDSM conflict-free)
// byte offsets into dynamic smem
#define OFF_Q   0
#define OFF_K   (OFF_Q + FBM*STRH*2)          // 18432
#define OFF_VT  (OFF_K + 2*FBN*STRH*2)        // 36864
#define OFF_MQ  (OFF_VT + 2*FBN*STRH*2)       // 55296 (floats)
#define OFF_MK  (OFF_MQ + FBM*4)              // 55808
#define FSM_BYTES (OFF_MK + 2*FBN*4)          // 56320

__global__ __launch_bounds__(128, 2) void attn_mma_kernel(const float* __restrict__ mask,
                                                          float* __restrict__ out) {
    extern __shared__ char smc[];
    const uint32_t smb = smem_u32(smc);
    const uint32_t sQ  = smb + OFF_Q;
    const uint32_t sK  = smb + OFF_K;
    const uint32_t sVT = smb + OFF_VT;
    const uint32_t sMQ = smb + OFF_MQ;
    const uint32_t sMK = smb + OFF_MK;

    float* mq = (float*)(smc + OFF_MQ);
    float* mk = (float*)(smc + OFF_MK);

    const int bh = blockIdx.y;
    const int b  = bh >> 4;
    const int h  = bh & 15;
    const int r0 = blockIdx.x * FBM;

    const int tid  = threadIdx.x;
    const int wid  = tid >> 5;
    const int lane = tid & 31;
    const int g    = lane >> 2;
    const int t    = lane & 3;
    const int lrow = lane & 15;
    const int lcol = (lane >> 4) << 3;
    const int wm   = wid * 32;

    const __half* Qg  = g_q  + (size_t)bh * NN * HD;
    const __half* Kg  = g_k  + (size_t)bh * NN * HD;
    const __half* Vtg = g_vt + (size_t)bh * HD * NN;

    auto issue_kv = [&](int kt) {
        const int buf = kt & 1;
        const int c0 = kt * FBN;
#pragma unroll
        for (int p = 0; p < 4; p++) {
            int idx = p * 128 + tid;          // 512 chunks each
            int r = idx >> 3, ch = (idx & 7) * 8;
            CP_ASYNC16(sK + (uint32_t)((buf * FBN + r) * STRH + ch) * 2,
                       Kg + (size_t)(c0 + r) * HD + ch);
            CP_ASYNC16(sVT + (uint32_t)((buf * FBN + r) * STRH + ch) * 2,
                       Vtg + (size_t)r * NN + c0 + ch);
        }
        if (tid < 16)
            CP_ASYNC16(sMK + (uint32_t)(buf * FBN + tid * 4) * 4,
                       mask + (size_t)b * NN + c0 + tid * 4);
    };

    // Prologue: Q tile + row mask, then KV tiles 0 and 1
    {
#pragma unroll
        for (int p = 0; p < 8; p++) {
            int idx = p * 128 + tid;          // 1024 chunks
            int r = idx >> 3, ch = (idx & 7) * 8;
            CP_ASYNC16(sQ + (uint32_t)(r * STRH + ch) * 2,
                       Qg + (size_t)(r0 + r) * HD + ch);
        }
        if (tid < 32)
            CP_ASYNC16(sMQ + (uint32_t)(tid * 4) * 4,
                       mask + (size_t)b * NN + r0 + tid * 4);
        CP_COMMIT();
        issue_kv(0); CP_COMMIT();
        issue_kv(1); CP_COMMIT();
    }

    // kt-invariant ldmatrix base for Q
    const uint32_t qaddr = sQ + (uint32_t)((wm + lrow) * STRH + lcol) * 2;

    float o[2][8][4];
    float m_lo[2], m_hi[2], l_lo[2], l_hi[2];
#pragma unroll
    for (int mi = 0; mi < 2; mi++) {
        m_lo[mi] = -1e30f; m_hi[mi] = -1e30f;
        l_lo[mi] = 0.0f;   l_hi[mi] = 0.0f;
#pragma unroll
        for (int ni = 0; ni < 8; ni++)
#pragma unroll
            for (int j = 0; j < 4; j++) o[mi][ni][j] = 0.0f;
    }

    const uint32_t FULL = 0xffffffffu;

    for (int kt = 0; kt < FNT; kt++) {
        CP_WAIT1();              // Q + current KV tile resident
        __syncthreads();
        const int kb = (kt & 1) * FBN;
        const uint32_t kaddr = sK  + (uint32_t)((kb + lrow) * STRH + lcol) * 2;
        const uint32_t vaddr = sVT + (uint32_t)((kb + lrow) * STRH + lcol) * 2;

        // row-mask values (log2e-scaled)
        const float mq_l2[2] = { mq[wm + g] * LOG2E,      mq[wm + 16 + g] * LOG2E };
        const float mq_h2[2] = { mq[wm + g + 8] * LOG2E,  mq[wm + 16 + g + 8] * LOG2E };
        float k0v[8], k1v[8];
#pragma unroll
        for (int ni = 0; ni < 8; ni++) {
            k0v[ni] = mk[kb + ni * 8 + 2 * t];
            k1v[ni] = mk[kb + ni * 8 + 2 * t + 1];
        }

        // ---- S = Q K^T : 4 k16 steps, ldmatrix Q and K fragments ----
        float sA[2][8][4];
#pragma unroll
        for (int mi = 0; mi < 2; mi++)
#pragma unroll
            for (int ni = 0; ni < 8; ni++)
#pragma unroll
                for (int j = 0; j < 4; j++) sA[mi][ni][j] = 0.0f;

#pragma unroll
        for (int ks = 0; ks < 4; ks++) {
            uint32_t qf0[4], qf1[4];
            ldsm_x4(qf0, qaddr + ks * 32);
            ldsm_x4(qf1, qaddr + (16 * STRH * 2) + ks * 32);
#pragma unroll
            for (int p = 0; p < 4; p++) {
                uint32_t kf[4];
                ldsm_x4(kf, kaddr + p * (16 * STRH * 2) + ks * 32);
                mma_f16(sA[0][2 * p],     qf0, kf[0], kf[2]);
                mma_f16(sA[0][2 * p + 1], qf0, kf[1], kf[3]);
                mma_f16(sA[1][2 * p],     qf1, kf[0], kf[2]);
                mma_f16(sA[1][2 * p + 1], qf1, kf[1], kf[3]);
            }
        }

        // ---- mask (1 fma) + online softmax in log2 domain; pack P ----
        uint32_t ph[2][4][4];     // packed P A-fragments
#pragma unroll
        for (int mi = 0; mi < 2; mi++) {
            float mx_lo = -1e30f, mx_hi = -1e30f;
#pragma unroll
            for (int ni = 0; ni < 8; ni++) {
                sA[mi][ni][0] = fmaf(-mq_l2[mi], k0v[ni], sA[mi][ni][0]);
                sA[mi][ni][1] = fmaf(-mq_l2[mi], k1v[ni], sA[mi][ni][1]);
                sA[mi][ni][2] = fmaf(-mq_h2[mi], k0v[ni], sA[mi][ni][2]);
                sA[mi][ni][3] = fmaf(-mq_h2[mi], k1v[ni], sA[mi][ni][3]);
                mx_lo = fmaxf(mx_lo, fmaxf(sA[mi][ni][0], sA[mi][ni][1]));
                mx_hi = fmaxf(mx_hi, fmaxf(sA[mi][ni][2], sA[mi][ni][3]));
            }
            mx_lo = fmaxf(mx_lo, __shfl_xor_sync(FULL, mx_lo, 1));
            mx_lo = fmaxf(mx_lo, __shfl_xor_sync(FULL, mx_lo, 2));
            mx_hi = fmaxf(mx_hi, __shfl_xor_sync(FULL, mx_hi, 1));
            mx_hi = fmaxf(mx_hi, __shfl_xor_sync(FULL, mx_hi, 2));

            const float mnew_lo = fmaxf(m_lo[mi], mx_lo);
            const float mnew_hi = fmaxf(m_hi[mi], mx_hi);
            const float fac_lo = exp2f_fast(m_lo[mi] - mnew_lo);
            const float fac_hi = exp2f_fast(m_hi[mi] - mnew_hi);

            float rs_lo = 0.0f, rs_hi = 0.0f;
#pragma unroll
            for (int ni = 0; ni < 8; ni++) {
                sA[mi][ni][0] = exp2f_fast(sA[mi][ni][0] - mnew_lo);
                sA[mi][ni][1] = exp2f_fast(sA[mi][ni][1] - mnew_lo);
                sA[mi][ni][2] = exp2f_fast(sA[mi][ni][2] - mnew_hi);
                sA[mi][ni][3] = exp2f_fast(sA[mi][ni][3] - mnew_hi);
                rs_lo += sA[mi][ni][0] + sA[mi][ni][1];
                rs_hi += sA[mi][ni][2] + sA[mi][ni][3];
            }
            rs_lo += __shfl_xor_sync(FULL, rs_lo, 1);
            rs_lo += __shfl_xor_sync(FULL, rs_lo, 2);
            rs_hi += __shfl_xor_sync(FULL, rs_hi, 1);
            rs_hi += __shfl_xor_sync(FULL, rs_hi, 2);

            l_lo[mi] = fmaf(l_lo[mi], fac_lo, rs_lo);  m_lo[mi] = mnew_lo;
            l_hi[mi] = fmaf(l_hi[mi], fac_hi, rs_hi);  m_hi[mi] = mnew_hi;
#pragma unroll
            for (int ni = 0; ni < 8; ni++) {
                o[mi][ni][0] *= fac_lo; o[mi][ni][1] *= fac_lo;
                o[mi][ni][2] *= fac_hi; o[mi][ni][3] *= fac_hi;
            }
            // pack P now so sA is dead before the PV loop
#pragma unroll
            for (int ks = 0; ks < 4; ks++) {
                ph[mi][ks][0] = f2h2(sA[mi][2 * ks][0],     sA[mi][2 * ks][1]);
                ph[mi][ks][1] = f2h2(sA[mi][2 * ks][2],     sA[mi][2 * ks][3]);
                ph[mi][ks][2] = f2h2(sA[mi][2 * ks + 1][0], sA[mi][2 * ks + 1][1]);
                ph[mi][ks][3] = f2h2(sA[mi][2 * ks + 1][2], sA[mi][2 * ks + 1][3]);
            }
        }

        // ---- O += P V : ldmatrix V fragments ----
#pragma unroll
        for (int ks = 0; ks < 4; ks++) {
#pragma unroll
            for (int p = 0; p < 4; p++) {
                uint32_t vf[4];
                ldsm_x4(vf, vaddr + p * (16 * STRH * 2) + ks * 32);
                mma_f16(o[0][2 * p],     ph[0][ks], vf[0], vf[2]);
                mma_f16(o[0][2 * p + 1], ph[0][ks], vf[1], vf[3]);
                mma_f16(o[1][2 * p],     ph[1][ks], vf[0], vf[2]);
                mma_f16(o[1][2 * p + 1], ph[1][ks], vf[1], vf[3]);
            }
        }

        __syncthreads();
        if (kt + 2 < FNT) issue_kv(kt + 2);
        CP_COMMIT();
    }

    // Output: out[b][n][h*64+d]
#pragma unroll
    for (int mi = 0; mi < 2; mi++) {
        const float inv_lo = 1.0f / l_lo[mi];
        const float inv_hi = 1.0f / l_hi[mi];
        const int row = r0 + wm + mi * 16 + g;
#pragma unroll
        for (int ni = 0; ni < 8; ni++) {
            const int col = h * HD + ni * 8 + 2 * t;
            *(float2*)&out[((size_t)(b * NN + row)) * CC + col] =
                make_float2(o[mi][ni][0] * inv_lo, o[mi][ni][1] * inv_lo);
            *(float2*)&out[((size_t)(b * NN + row + 8)) * CC + col] =
                make_float2(o[mi][ni][2] * inv_hi, o[mi][ni][3] * inv_hi);
        }
    }
}

// ---------------------------------------------------------------------------
extern "C" void kernel_launch(void* const* d_in, const int* in_sizes, int n_in,
                              void* d_out, int out_size) {
    const float* inputs = (const float*)d_in[0];   // [B,N,C]
    const float* mask   = (const float*)d_in[1];   // [B,N]
    const float* W      = (const float*)d_in[2];   // [C,3C]
    float* out = (float*)d_out;                    // [B,N,C]

    cudaFuncSetAttribute((const void*)qkv_mma_kernel,
                         cudaFuncAttributeMaxDynamicSharedMemorySize, QSM_BYTES);
    cudaFuncSetAttribute((const void*)attn_mma_kernel,
                         cudaFuncAttributeMaxDynamicSharedMemorySize, FSM_BYTES);

    pe_add_kernel<<<(NN * CC + 255) / 256, 256>>>(inputs);
    wt_kernel<<<dim3(N3C / 32, K_TOT / 32), dim3(32, 8)>>>(W);
    qkv_mma_kernel<<<dim3(N3C / GBN, M_TOT / GBM), 256, QSM_BYTES>>>();
    attn_mma_kernel<<<dim3(NN / FBM, BB * HH), 128, FSM_BYTES>>>(mask, out);
}

// round 10
// speedup vs baseline: 1.0579x; 1.0291x over previous
#include <cuda_runtime.h>
#include <cuda_fp16.h>
#include <math.h>
#include <stdint.h>

// Problem constants
#define BB 4
#define NN 2048
#define CC 1024
#define HH 16
#define HD 64
#define M_TOT (BB*NN)    // 8192
#define N3C   (3*CC)     // 3072
#define K_TOT CC         // 1024

#define LOG2E 1.4426950408889634f
#define QSCALE (0.125f * LOG2E)   // 64^-0.5 * log2(e), folded into Q

// Scratch (static device globals — allocation-free per harness rules)
__device__ __half g_x [M_TOT * CC];        // x = inputs + PE (fp16)  [8192,1024]
__device__ __half g_wt[N3C * CC];          // W^T (fp16)              [3072,1024]
__device__ __half g_q [BB*HH*NN*HD];       // [B,H,N,hd], pre-scaled by QSCALE
__device__ __half g_k [BB*HH*NN*HD];       // [B,H,N,hd]
__device__ __half g_vt[BB*HH*HD*NN];       // V transposed: [B,H,hd,N]

// ---------------------------------------------------------------------------
// Helpers
// ---------------------------------------------------------------------------
__device__ __forceinline__ void mma_f16(float* c, const uint32_t* a,
                                        uint32_t b0, uint32_t b1) {
    asm volatile(
        "mma.sync.aligned.m16n8k16.row.col.f32.f16.f16.f32 "
        "{%0,%1,%2,%3}, {%4,%5,%6,%7}, {%8,%9}, {%0,%1,%2,%3};"
        : "+f"(c[0]), "+f"(c[1]), "+f"(c[2]), "+f"(c[3])
        : "r"(a[0]), "r"(a[1]), "r"(a[2]), "r"(a[3]), "r"(b0), "r"(b1));
}

__device__ __forceinline__ void ldsm_x4(uint32_t* r, uint32_t a) {
    asm volatile("ldmatrix.sync.aligned.m8n8.x4.shared.b16 {%0,%1,%2,%3}, [%4];"
        : "=r"(r[0]), "=r"(r[1]), "=r"(r[2]), "=r"(r[3]) : "r"(a));
}

__device__ __forceinline__ uint32_t f2h2(float lo, float hi) {
    __half2 h = __floats2half2_rn(lo, hi);
    return *(uint32_t*)&h;
}

__device__ __forceinline__ float exp2f_fast(float x) {
    float y;
    asm("ex2.approx.ftz.f32 %0, %1;" : "=f"(y) : "f"(x));
    return y;
}

// packed half2 exp2 — one MUFU op for two probabilities
__device__ __forceinline__ uint32_t h2exp2(uint32_t x) {
    uint32_t y;
    asm("ex2.approx.f16x2 %0, %1;" : "=r"(y) : "r"(x));
    return y;
}

__device__ __forceinline__ uint32_t smem_u32(const void* p) {
    uint32_t a;
    asm("{ .reg .u64 t; cvta.to.shared.u64 t, %1; cvt.u32.u64 %0, t; }"
        : "=r"(a) : "l"(p));
    return a;
}

#define CP_ASYNC16(dst, src) \
    asm volatile("cp.async.cg.shared.global [%0], [%1], 16;" \
        :: "r"(dst), "l"(src) : "memory")
#define CP_COMMIT() asm volatile("cp.async.commit_group;" ::: "memory")
#define CP_WAIT1()  asm volatile("cp.async.wait_group 1;" ::: "memory")

// ---------------------------------------------------------------------------
// Kernel 1: x = inputs + sinusoidal PE -> fp16
// ---------------------------------------------------------------------------
__global__ void pe_add_kernel(const float* __restrict__ in) {
    int idx = blockIdx.x * blockDim.x + threadIdx.x;
    if (idx >= NN * CC) return;
    int c = idx & (CC - 1);
    int n = idx >> 10;
    float e = (float)(2 * (c >> 1)) / (float)CC;
    float rate = powf(10000.0f, -e);
    float ang = (float)n * rate;
    float s, co;
    sincosf(ang, &s, &co);
    float pe = (c & 1) ? co : s;
#pragma unroll
    for (int b = 0; b < BB; b++) {
        g_x[b * (NN * CC) + idx] = __float2half_rn(in[b * (NN * CC) + idx] + pe);
    }
}

// ---------------------------------------------------------------------------
// Kernel 1b: W^T -> fp16. W [1024,3072] -> g_wt [3072,1024]
// ---------------------------------------------------------------------------
__global__ __launch_bounds__(256) void wt_kernel(const float* __restrict__ W) {
    __shared__ float t[32][33];
    int tx = threadIdx.x, ty = threadIdx.y;
    int n0 = blockIdx.x * 32;
    int k0 = blockIdx.y * 32;
#pragma unroll
    for (int i = 0; i < 32; i += 8)
        t[ty + i][tx] = W[(size_t)(k0 + ty + i) * N3C + n0 + tx];
    __syncthreads();
#pragma unroll
    for (int i = 0; i < 32; i += 8)
        g_wt[(size_t)(n0 + ty + i) * K_TOT + k0 + tx] = __float2half_rn(t[tx][ty + i]);
}

// ---------------------------------------------------------------------------
// Kernel 2: QKV GEMM, mma.sync fp16 (m16n8k16), 3-stage cp.async pipeline,
// ldmatrix fragment loads (neutral vs scalar here). Epilogue: Q pre-scaled;
// V transposed.
// ---------------------------------------------------------------------------
#define GBM 128
#define GBN 128
#define GBK 32
#define GSTRH 40                 // halves per row (80B, LDSM conflict-free)
#define GNKT (K_TOT / GBK)       // 32
#define QSTH (GBM * GSTRH)       // halves per tile per stage (5120)
#define QSM_BYTES (3 * 2 * QSTH * 2)   // 61440

__global__ __launch_bounds__(256, 2) void qkv_mma_kernel() {
    extern __shared__ char qsm[];
    const uint32_t smb = smem_u32(qsm);

    const int tid  = threadIdx.x;
    const int wid  = tid >> 5;
    const int lane = tid & 31;
    const int g    = lane >> 2;    // 0..7
    const int t    = lane & 3;     // 0..3
    const int lrow = lane & 15;
    const int lcol = (lane >> 4) << 3;
    const int wm   = (wid & 1) * 64;
    const int wn   = (wid >> 1) * 32;
    const int row0 = blockIdx.y * GBM;
    const int col0 = blockIdx.x * GBN;

    float acc[4][4][4];
#pragma unroll
    for (int mi = 0; mi < 4; mi++)
#pragma unroll
        for (int ni = 0; ni < 4; ni++)
#pragma unroll
            for (int j = 0; j < 4; j++) acc[mi][ni][j] = 0.0f;

    auto issue = [&](int s, int kt) {
        const int k0 = kt * GBK;
        const uint32_t dA = smb + (uint32_t)(s * 2 * QSTH) * 2;
        const uint32_t dB = dA + (uint32_t)QSTH * 2;
#pragma unroll
        for (int p = 0; p < 2; p++) {
            int idx = p * 256 + tid;
            int row = idx >> 2, ch = (idx & 3) * 8;
            CP_ASYNC16(dA + (uint32_t)(row * GSTRH + ch) * 2,
                       &g_x[(size_t)(row0 + row) * K_TOT + k0 + ch]);
            CP_ASYNC16(dB + (uint32_t)(row * GSTRH + ch) * 2,
                       &g_wt[(size_t)(col0 + row) * K_TOT + k0 + ch]);
        }
    };

    issue(0, 0); CP_COMMIT();
    issue(1, 1); CP_COMMIT();

    for (int kt = 0; kt < GNKT; kt++) {
        CP_WAIT1();
        __syncthreads();
        const uint32_t sbase = smb + (uint32_t)((kt % 3) * 2 * QSTH) * 2;
        const uint32_t aaddr = sbase + (uint32_t)((wm + lrow) * GSTRH + lcol) * 2;
        const uint32_t baddr = sbase + (uint32_t)QSTH * 2
                             + (uint32_t)((wn + lrow) * GSTRH + lcol) * 2;

#pragma unroll
        for (int ks = 0; ks < 2; ks++) {
            uint32_t af[4][4], bf4[2][4];
#pragma unroll
            for (int mi = 0; mi < 4; mi++)
                ldsm_x4(af[mi], aaddr + mi * (16 * GSTRH * 2) + ks * 32);
#pragma unroll
            for (int p = 0; p < 2; p++)
                ldsm_x4(bf4[p], baddr + p * (16 * GSTRH * 2) + ks * 32);
#pragma unroll
            for (int mi = 0; mi < 4; mi++) {
                mma_f16(acc[mi][0], af[mi], bf4[0][0], bf4[0][2]);
                mma_f16(acc[mi][1], af[mi], bf4[0][1], bf4[0][3]);
                mma_f16(acc[mi][2], af[mi], bf4[1][0], bf4[1][2]);
                mma_f16(acc[mi][3], af[mi], bf4[1][1], bf4[1][3]);
            }
        }
        __syncthreads();
        if (kt + 2 < GNKT) issue((kt + 2) % 3, kt + 2);
        CP_COMMIT();
    }

    // Epilogue: Q pre-scaled by QSCALE; Q/K -> [B,H,N,hd], V -> [B,H,hd,N]
#pragma unroll
    for (int mi = 0; mi < 4; mi++) {
        const int row = row0 + wm + mi * 16 + g;
        const int b = row >> 11;
        const int n = row & (NN - 1);
#pragma unroll
        for (int ni = 0; ni < 4; ni++) {
            const int col = col0 + wn + ni * 8 + 2 * t;
            const int tt = col >> 10;
            const int h = (col >> 6) & 15;
            const int d = col & 63;
            const size_t bh = (size_t)(b * HH + h);
            if (tt == 0) {
                __half2* p0 = (__half2*)(g_q + (bh * NN + n) * HD + d);
                *p0 = __floats2half2_rn(acc[mi][ni][0] * QSCALE, acc[mi][ni][1] * QSCALE);
                __half2* p1 = (__half2*)(g_q + (bh * NN + n + 8) * HD + d);
                *p1 = __floats2half2_rn(acc[mi][ni][2] * QSCALE, acc[mi][ni][3] * QSCALE);
            } else if (tt == 1) {
                __half2* p0 = (__half2*)(g_k + (bh * NN + n) * HD + d);
                *p0 = __floats2half2_rn(acc[mi][ni][0], acc[mi][ni][1]);
                __half2* p1 = (__half2*)(g_k + (bh * NN + n + 8) * HD + d);
                *p1 = __floats2half2_rn(acc[mi][ni][2], acc[mi][ni][3]);
            } else {
                __half* vt = g_vt + bh * HD * NN;
                vt[(size_t)d * NN + n]           = __float2half_rn(acc[mi][ni][0]);
                vt[(size_t)(d + 1) * NN + n]     = __float2half_rn(acc[mi][ni][1]);
                vt[(size_t)d * NN + n + 8]       = __float2half_rn(acc[mi][ni][2]);
                vt[(size_t)(d + 1) * NN + n + 8] = __float2half_rn(acc[mi][ni][3]);
            }
        }
    }
}

// ---------------------------------------------------------------------------
// Kernel 3: Flash attention, mma.sync fp16 (m16n8k16), log2-domain softmax.
// R7 body (scalar LDS fragment loads — faster than ldmatrix here) plus:
//   * packed ex2.approx.f16x2 (MUFU halved; output IS the fp16 P fragment)
//   * l accumulated by an all-ones B-tile MMA (P·1), so the row-sum shfl
//     machinery disappears and normalization uses the exact same fp16 P.
// ---------------------------------------------------------------------------
#define FBM 128
#define FBN 64
#define FNT (NN / FBN)     // 32
#define STRH 72            // halves per row (144B, conflict-free)
// byte offsets into dynamic smem
#define OFF_Q   0
#define OFF_K   (OFF_Q + FBM*STRH*2)          // 18432
#define OFF_VT  (OFF_K + 2*FBN*STRH*2)        // 36864
#define OFF_MQ  (OFF_VT + 2*FBN*STRH*2)       // 55296 (floats)
#define OFF_MK  (OFF_MQ + FBM*4)              // 55808
#define FSM_BYTES (OFF_MK + 2*FBN*4)          // 56320

__global__ __launch_bounds__(128, 2) void attn_mma_kernel(const float* __restrict__ mask,
                                                          float* __restrict__ out) {
    extern __shared__ char smc[];
    const uint32_t smb = smem_u32(smc);
    const uint32_t sQ  = smb + OFF_Q;
    const uint32_t sK  = smb + OFF_K;
    const uint32_t sVT = smb + OFF_VT;
    const uint32_t sMQ = smb + OFF_MQ;
    const uint32_t sMK = smb + OFF_MK;

    __half* Qs  = (__half*)(smc + OFF_Q);
    __half* Ks  = (__half*)(smc + OFF_K);
    __half* Vts = (__half*)(smc + OFF_VT);
    float*  mq  = (float*)(smc + OFF_MQ);
    float*  mk  = (float*)(smc + OFF_MK);

    const int bh = blockIdx.y;
    const int b  = bh >> 4;
    const int h  = bh & 15;
    const int r0 = blockIdx.x * FBM;

    const int tid  = threadIdx.x;
    const int wid  = tid >> 5;
    const int lane = tid & 31;
    const int g    = lane >> 2;
    const int t    = lane & 3;
    const int wm   = wid * 32;

    const __half* Qg  = g_q  + (size_t)bh * NN * HD;
    const __half* Kg  = g_k  + (size_t)bh * NN * HD;
    const __half* Vtg = g_vt + (size_t)bh * HD * NN;

    auto issue_kv = [&](int kt) {
        const int buf = kt & 1;
        const int c0 = kt * FBN;
#pragma unroll
        for (int p = 0; p < 4; p++) {
            int idx = p * 128 + tid;
            int r = idx >> 3, ch = (idx & 7) * 8;
            CP_ASYNC16(sK + (uint32_t)((buf * FBN + r) * STRH + ch) * 2,
                       Kg + (size_t)(c0 + r) * HD + ch);
            CP_ASYNC16(sVT + (uint32_t)((buf * FBN + r) * STRH + ch) * 2,
                       Vtg + (size_t)r * NN + c0 + ch);
        }
        if (tid < 16)
            CP_ASYNC16(sMK + (uint32_t)(buf * FBN + tid * 4) * 4,
                       mask + (size_t)b * NN + c0 + tid * 4);
    };

    // Prologue: Q tile + row mask, then KV tiles 0 and 1
    {
#pragma unroll
        for (int p = 0; p < 8; p++) {
            int idx = p * 128 + tid;
            int r = idx >> 3, ch = (idx & 7) * 8;
            CP_ASYNC16(sQ + (uint32_t)(r * STRH + ch) * 2,
                       Qg + (size_t)(r0 + r) * HD + ch);
        }
        if (tid < 32)
            CP_ASYNC16(sMQ + (uint32_t)(tid * 4) * 4,
                       mask + (size_t)b * NN + r0 + tid * 4);
        CP_COMMIT();
        issue_kv(0); CP_COMMIT();
        issue_kv(1); CP_COMMIT();
    }

    float o[2][8][4];
    float l_acc[2][4];          // l in MMA C-fragment: [0]=row lo, [2]=row hi
    float m_lo[2], m_hi[2];
#pragma unroll
    for (int mi = 0; mi < 2; mi++) {
        m_lo[mi] = -1e30f; m_hi[mi] = -1e30f;
#pragma unroll
        for (int j = 0; j < 4; j++) l_acc[mi][j] = 0.0f;
#pragma unroll
        for (int ni = 0; ni < 8; ni++)
#pragma unroll
            for (int j = 0; j < 4; j++) o[mi][ni][j] = 0.0f;
    }

    const uint32_t FULL = 0xffffffffu;
    const uint32_t ONES = 0x3C003C00u;   // half2(1.0, 1.0)

    for (int kt = 0; kt < FNT; kt++) {
        CP_WAIT1();
        __syncthreads();
        const int kb = (kt & 1) * FBN;

        // row-mask values (log2e-scaled)
        const float mq_l2[2] = { mq[wm + g] * LOG2E,      mq[wm + 16 + g] * LOG2E };
        const float mq_h2[2] = { mq[wm + g + 8] * LOG2E,  mq[wm + 16 + g + 8] * LOG2E };
        float k0v[8], k1v[8];
#pragma unroll
        for (int ni = 0; ni < 8; ni++) {
            k0v[ni] = mk[kb + ni * 8 + 2 * t];
            k1v[ni] = mk[kb + ni * 8 + 2 * t + 1];
        }

        // ---- S = Q K^T : 4 k16 steps (scalar-LDS fragments, R7 style) ----
        float sA[2][8][4];
#pragma unroll
        for (int mi = 0; mi < 2; mi++)
#pragma unroll
            for (int ni = 0; ni < 8; ni++)
#pragma unroll
                for (int j = 0; j < 4; j++) sA[mi][ni][j] = 0.0f;

#pragma unroll
        for (int ks = 0; ks < 4; ks++) {
            const int k0 = ks * 16;
            uint32_t af[2][4];
#pragma unroll
            for (int mi = 0; mi < 2; mi++) {
                const int rq = (wm + mi * 16 + g) * STRH + k0 + 2 * t;
                af[mi][0] = *(const uint32_t*)&Qs[rq];
                af[mi][1] = *(const uint32_t*)&Qs[rq + 8 * STRH];
                af[mi][2] = *(const uint32_t*)&Qs[rq + 8];
                af[mi][3] = *(const uint32_t*)&Qs[rq + 8 * STRH + 8];
            }
#pragma unroll
            for (int ni = 0; ni < 8; ni++) {
                const int rk = (kb + ni * 8 + g) * STRH + k0 + 2 * t;
                const uint32_t b0 = *(const uint32_t*)&Ks[rk];
                const uint32_t b1 = *(const uint32_t*)&Ks[rk + 8];
                mma_f16(sA[0][ni], af[0], b0, b1);
                mma_f16(sA[1][ni], af[1], b0, b1);
            }
        }

        // ---- mask (1 fma) + online softmax; P via packed f16x2 ex2 ----
        uint32_t ph[2][4][4];     // packed fp16 P A-fragments
#pragma unroll
        for (int mi = 0; mi < 2; mi++) {
            float mx_lo = -1e30f, mx_hi = -1e30f;
#pragma unroll
            for (int ni = 0; ni < 8; ni++) {
                sA[mi][ni][0] = fmaf(-mq_l2[mi], k0v[ni], sA[mi][ni][0]);
                sA[mi][ni][1] = fmaf(-mq_l2[mi], k1v[ni], sA[mi][ni][1]);
                sA[mi][ni][2] = fmaf(-mq_h2[mi], k0v[ni], sA[mi][ni][2]);
                sA[mi][ni][3] = fmaf(-mq_h2[mi], k1v[ni], sA[mi][ni][3]);
                mx_lo = fmaxf(mx_lo, fmaxf(sA[mi][ni][0], sA[mi][ni][1]));
                mx_hi = fmaxf(mx_hi, fmaxf(sA[mi][ni][2], sA[mi][ni][3]));
            }
            mx_lo = fmaxf(mx_lo, __shfl_xor_sync(FULL, mx_lo, 1));
            mx_lo = fmaxf(mx_lo, __shfl_xor_sync(FULL, mx_lo, 2));
            mx_hi = fmaxf(mx_hi, __shfl_xor_sync(FULL, mx_hi, 1));
            mx_hi = fmaxf(mx_hi, __shfl_xor_sync(FULL, mx_hi, 2));

            const float mnew_lo = fmaxf(m_lo[mi], mx_lo);
            const float mnew_hi = fmaxf(m_hi[mi], mx_hi);
            const float fac_lo = exp2f_fast(m_lo[mi] - mnew_lo);
            const float fac_hi = exp2f_fast(m_hi[mi] - mnew_hi);
            m_lo[mi] = mnew_lo;  m_hi[mi] = mnew_hi;

            // rescale running O and l
            l_acc[mi][0] *= fac_lo;
            l_acc[mi][2] *= fac_hi;
#pragma unroll
            for (int ni = 0; ni < 8; ni++) {
                o[mi][ni][0] *= fac_lo; o[mi][ni][1] *= fac_lo;
                o[mi][ni][2] *= fac_hi; o[mi][ni][3] *= fac_hi;
            }

            // P = exp2(s - mnew) computed two-at-a-time in fp16
#pragma unroll
            for (int ks = 0; ks < 4; ks++) {
                ph[mi][ks][0] = h2exp2(f2h2(sA[mi][2 * ks][0] - mnew_lo,
                                            sA[mi][2 * ks][1] - mnew_lo));
                ph[mi][ks][1] = h2exp2(f2h2(sA[mi][2 * ks][2] - mnew_hi,
                                            sA[mi][2 * ks][3] - mnew_hi));
                ph[mi][ks][2] = h2exp2(f2h2(sA[mi][2 * ks + 1][0] - mnew_lo,
                                            sA[mi][2 * ks + 1][1] - mnew_lo));
                ph[mi][ks][3] = h2exp2(f2h2(sA[mi][2 * ks + 1][2] - mnew_hi,
                                            sA[mi][2 * ks + 1][3] - mnew_hi));
            }
        }

        // ---- O += P V (scalar-LDS V fragments) and l += P·1 ----
#pragma unroll
        for (int ks = 0; ks < 4; ks++) {
            const int k0 = ks * 16;
#pragma unroll
            for (int ni = 0; ni < 8; ni++) {
                const int rv = (kb + ni * 8 + g) * STRH + k0 + 2 * t;
                const uint32_t b0 = *(const uint32_t*)&Vts[rv];
                const uint32_t b1 = *(const uint32_t*)&Vts[rv + 8];
                mma_f16(o[0][ni], ph[0][ks], b0, b1);
                mma_f16(o[1][ni], ph[1][ks], b0, b1);
            }
            mma_f16(l_acc[0], ph[0][ks], ONES, ONES);
            mma_f16(l_acc[1], ph[1][ks], ONES, ONES);
        }

        __syncthreads();
        if (kt + 2 < FNT) issue_kv(kt + 2);
        CP_COMMIT();
    }

    // Output: out[b][n][h*64+d]
#pragma unroll
    for (int mi = 0; mi < 2; mi++) {
        const float inv_lo = 1.0f / l_acc[mi][0];
        const float inv_hi = 1.0f / l_acc[mi][2];
        const int row = r0 + wm + mi * 16 + g;
#pragma unroll
        for (int ni = 0; ni < 8; ni++) {
            const int col = h * HD + ni * 8 + 2 * t;
            *(float2*)&out[((size_t)(b * NN + row)) * CC + col] =
                make_float2(o[mi][ni][0] * inv_lo, o[mi][ni][1] * inv_lo);
            *(float2*)&out[((size_t)(b * NN + row + 8)) * CC + col] =
                make_float2(o[mi][ni][2] * inv_hi, o[mi][ni][3] * inv_hi);
        }
    }
}

// ---------------------------------------------------------------------------
extern "C" void kernel_launch(void* const* d_in, const int* in_sizes, int n_in,
                              void* d_out, int out_size) {
    const float* inputs = (const float*)d_in[0];   // [B,N,C]
    const float* mask   = (const float*)d_in[1];   // [B,N]
    const float* W      = (const float*)d_in[2];   // [C,3C]
    float* out = (float*)d_out;                    // [B,N,C]

    cudaFuncSetAttribute((const void*)qkv_mma_kernel,
                         cudaFuncAttributeMaxDynamicSharedMemorySize, QSM_BYTES);
    cudaFuncSetAttribute((const void*)attn_mma_kernel,
                         cudaFuncAttributeMaxDynamicSharedMemorySize, FSM_BYTES);

    pe_add_kernel<<<(NN * CC + 255) / 256, 256>>>(inputs);
    wt_kernel<<<dim3(N3C / 32, K_TOT / 32), dim3(32, 8)>>>(W);
    qkv_mma_kernel<<<dim3(N3C / GBN, M_TOT / GBM), 256, QSM_BYTES>>>();
    attn_mma_kernel<<<dim3(NN / FBM, BB * HH), 128, FSM_BYTES>>>(mask, out);
}